// round 4
// baseline (speedup 1.0000x reference)
#include <cuda_runtime.h>
#include <stdint.h>

// Problem constants (fixed by the reference)
#define SEQ_LEN   2048
#define NUM_HEADS 16
#define BATCH     2
#define BIAS_PITCH 4096   // 2*SEQ_LEN-1 = 4095, padded to 4096

// Scratch: per-head bias indexed by t = (i - j) + (S-1)
//   t >= S-1  -> e1[t-(S-1), h]
//   t <  S-1  -> e2[(S-2)-t,  h]
__device__ float g_bias[NUM_HEADS * BIAS_PITCH];

__global__ void build_bias_kernel(const float* __restrict__ e1,
                                  const float* __restrict__ e2) {
    int idx = blockIdx.x * blockDim.x + threadIdx.x;
    const int total = NUM_HEADS * (2 * SEQ_LEN - 1);
    if (idx >= total) return;
    int h = idx / (2 * SEQ_LEN - 1);
    int t = idx - h * (2 * SEQ_LEN - 1);
    float v;
    if (t >= SEQ_LEN - 1) {
        v = e1[(t - (SEQ_LEN - 1)) * NUM_HEADS + h];
    } else {
        v = e2[((SEQ_LEN - 2) - t) * NUM_HEADS + h];
    }
    g_bias[h * BIAS_PITCH + t] = v;
}

// Each thread: 8 consecutive j-values (two float4) for one (h, i),
// written to both batch planes with streaming (evict-first) stores.
__global__ __launch_bounds__(256)
void write_out_kernel(float4* __restrict__ out) {
    // tid layout: j8 fastest (S/8 = 256), then i (2048), then h (16)
    unsigned tid = blockIdx.x * blockDim.x + threadIdx.x;
    unsigned j8 = tid & 255u;           // tid % 256
    unsigned rem = tid >> 8;            // tid / 256
    unsigned i = rem & 2047u;           // rem % 2048
    unsigned h = rem >> 11;             // rem / 2048

    int j0 = (int)(j8 << 3);
    // t for j = j0: t = i - j0 + (S-1); this thread reads t down to t-7.
    // Range: i in [0,2047], j0 in [0,2040] -> t in [7, 4094]; t-7 >= 0. In bounds.
    const float* __restrict__ bh =
        g_bias + h * BIAS_PITCH + ((int)i - j0 + (SEQ_LEN - 1));

    float4 v0, v1;
    v0.x = bh[0];   v0.y = bh[-1];  v0.z = bh[-2];  v0.w = bh[-3];
    v1.x = bh[-4];  v1.y = bh[-5];  v1.z = bh[-6];  v1.w = bh[-7];

    // out is float4-typed: 512 float4 per (h,i) row
    size_t row = (size_t)h * SEQ_LEN + i;                    // plane-row, batch 0
    size_t off0 = row * 512 + ((size_t)j8 << 1);
    size_t off1 = off0 + (size_t)NUM_HEADS * SEQ_LEN * 512;  // batch 1 plane

    __stcs(&out[off0],     v0);
    __stcs(&out[off0 + 1], v1);
    __stcs(&out[off1],     v0);
    __stcs(&out[off1 + 1], v1);
}

extern "C" void kernel_launch(void* const* d_in, const int* in_sizes, int n_in,
                              void* d_out, int out_size) {
    // metadata order: q (unused), e1, e2
    const float* e1 = (const float*)d_in[1];
    const float* e2 = (const float*)d_in[2];
    float4* out = (float4*)d_out;

    {
        const int total = NUM_HEADS * (2 * SEQ_LEN - 1);
        int threads = 256;
        int blocks = (total + threads - 1) / threads;
        build_bias_kernel<<<blocks, threads>>>(e1, e2);
    }
    {
        // threads = H * S * (S/8) = 16 * 2048 * 256 = 8,388,608
        unsigned total = NUM_HEADS * SEQ_LEN * (SEQ_LEN / 8);
        int threads = 256;
        unsigned blocks = total / threads;   // 32768
        write_out_kernel<<<blocks, threads>>>(out);
    }
}

// round 5
// speedup vs baseline: 1.8429x; 1.8429x over previous
#include <cuda_runtime.h>
#include <stdint.h>

// Problem constants (fixed by the reference)
#define SEQ_LEN   2048
#define NUM_HEADS 16
#define BATCH     2
#define BIAS_PITCH 4096   // 2*SEQ_LEN-1 = 4095, padded to 4096

// Scratch: per-head bias indexed by t = (i - j) + (S-1)
//   t >= S-1  -> e1[t-(S-1), h]
//   t <  S-1  -> e2[(S-2)-t,  h]
__device__ float g_bias[NUM_HEADS * BIAS_PITCH];

__global__ void build_bias_kernel(const float* __restrict__ e1,
                                  const float* __restrict__ e2) {
    int idx = blockIdx.x * blockDim.x + threadIdx.x;
    const int total = NUM_HEADS * (2 * SEQ_LEN - 1);
    if (idx >= total) return;
    int h = idx / (2 * SEQ_LEN - 1);
    int t = idx - h * (2 * SEQ_LEN - 1);
    float v;
    if (t >= SEQ_LEN - 1) {
        v = e1[(t - (SEQ_LEN - 1)) * NUM_HEADS + h];
    } else {
        v = e2[((SEQ_LEN - 2) - t) * NUM_HEADS + h];
    }
    g_bias[h * BIAS_PITCH + t] = v;
}

// Each thread: one float4 of bias for (h, i, j0..j0+3), stored to both batch
// planes. Lane-stride is 16B -> perfectly coalesced 128B-line warp stores.
// Single change vs the 82us baseline: streaming (evict-first) store hint.
__global__ __launch_bounds__(256)
void write_out_kernel(float4* __restrict__ out) {
    // tid layout: j4 fastest (S/4 = 512), then i (2048), then h (16)
    unsigned tid = blockIdx.x * blockDim.x + threadIdx.x;
    unsigned j4 = tid & 511u;           // tid % 512
    unsigned rem = tid >> 9;            // tid / 512
    unsigned i = rem & 2047u;           // rem % 2048
    unsigned h = rem >> 11;             // rem / 2048

    int j0 = (int)(j4 << 2);
    // t for j = j0: t = i - j0 + (S-1); accesses t, t-1, t-2, t-3.
    // Range: i in [0,2047], j0 in [0,2044] -> t in [3, 4094]; t-3 >= 0. In bounds.
    const float* __restrict__ bh =
        g_bias + h * BIAS_PITCH + ((int)i - j0 + (SEQ_LEN - 1));

    float4 v;
    v.x = bh[0];     // j0     -> t
    v.y = bh[-1];    // j0 + 1 -> t-1
    v.z = bh[-2];
    v.w = bh[-3];

    // out is float4-typed: S/4 = 512 float4 per row
    size_t row = (size_t)h * SEQ_LEN + i;                    // plane-row, batch 0
    size_t off0 = row * 512 + j4;
    size_t off1 = off0 + (size_t)NUM_HEADS * SEQ_LEN * 512;  // batch 1 plane

    __stcs(&out[off0], v);
    __stcs(&out[off1], v);
}

extern "C" void kernel_launch(void* const* d_in, const int* in_sizes, int n_in,
                              void* d_out, int out_size) {
    // metadata order: q (unused), e1, e2
    const float* e1 = (const float*)d_in[1];
    const float* e2 = (const float*)d_in[2];
    float4* out = (float4*)d_out;

    {
        const int total = NUM_HEADS * (2 * SEQ_LEN - 1);
        int threads = 256;
        int blocks = (total + threads - 1) / threads;
        build_bias_kernel<<<blocks, threads>>>(e1, e2);
    }
    {
        // threads = H * S * (S/4) = 16 * 2048 * 512 = 16,777,216
        unsigned total = NUM_HEADS * SEQ_LEN * (SEQ_LEN / 4);
        int threads = 256;
        unsigned blocks = total / threads;   // 65536
        write_out_kernel<<<blocks, threads>>>(out);
    }
}